// round 16
// baseline (speedup 1.0000x reference)
#include <cuda_runtime.h>
#include <cuda_bf16.h>
#include <math.h>
#include <stdint.h>

// ---------------- problem constants ----------------
#define HH      64
#define PP      64
#define NST     128
#define GG      8
#define DMODEL  2048
#define CSZ     256
#define LL      4096
#define INTER_  4096
#define CONVDIM_ 6144
#define PROJ_   10304
#define NCH     16
#define NBATCH  1024

// ---------------- fp32 scratch ----------------
__device__ float d_proj[(size_t)LL * PROJ_];
__device__ float d_conv[(size_t)LL * CONVDIM_];
__device__ float d_dt[(size_t)LL * HH];
__device__ float d_Acs[(size_t)HH * LL];
__device__ float d_states[(size_t)NBATCH * PP * NST];
__device__ float d_Y[(size_t)LL * INTER_];

// ---------------- bf16 hi/lo operand arrays ----------------
__device__ __nv_bfloat16 d_A1hi[(size_t)LL * DMODEL];
__device__ __nv_bfloat16 d_A1lo[(size_t)LL * DMODEL];
__device__ __nv_bfloat16 d_W1hi[(size_t)PROJ_ * DMODEL];
__device__ __nv_bfloat16 d_W1lo[(size_t)PROJ_ * DMODEL];
__device__ __nv_bfloat16 d_A2hi[(size_t)LL * INTER_];
__device__ __nv_bfloat16 d_A2lo[(size_t)LL * INTER_];
__device__ __nv_bfloat16 d_W2hi[(size_t)DMODEL * INTER_];
__device__ __nv_bfloat16 d_W2lo[(size_t)DMODEL * INTER_];

__device__ __nv_bfloat16 d_Bhi[(size_t)LL * 1024];   // B  [l][g*128+n]
__device__ __nv_bfloat16 d_Blo[(size_t)LL * 1024];
__device__ __nv_bfloat16 d_Chi2[(size_t)LL * 1024];  // C  [l][g*128+n]
__device__ __nv_bfloat16 d_Clo2[(size_t)LL * 1024];
__device__ __nv_bfloat16 d_BThi[(size_t)1024 * LL];  // B^T [g*128+n][l]
__device__ __nv_bfloat16 d_BTlo[(size_t)1024 * LL];
__device__ __nv_bfloat16 d_xThi[(size_t)INTER_ * LL];   // xdt^T   [h*64+p][l]
__device__ __nv_bfloat16 d_xTlo[(size_t)INTER_ * LL];
__device__ __nv_bfloat16 d_xdThi[(size_t)INTER_ * LL];  // (xdt*decay)^T
__device__ __nv_bfloat16 d_xdTlo[(size_t)INTER_ * LL];
__device__ __nv_bfloat16 d_pvhi[(size_t)NBATCH * PP * NST]; // prev [z][p][n]
__device__ __nv_bfloat16 d_pvlo[(size_t)NBATCH * PP * NST];

// ---------------- helpers ----------------
__device__ __forceinline__ uint32_t smem_u32(const void* p) {
    uint32_t a;
    asm("{ .reg .u64 t; cvta.to.shared.u64 t, %1; cvt.u32.u64 %0, t; }" : "=r"(a) : "l"(p));
    return a;
}
__device__ __forceinline__ void cpa16(uint32_t dst, const void* src) {
    asm volatile("cp.async.cg.shared.global [%0], [%1], 16;\n" :: "r"(dst), "l"(src));
}
#define CP_COMMIT() asm volatile("cp.async.commit_group;\n" ::: "memory")
#define CP_WAIT2()  asm volatile("cp.async.wait_group 2;\n" ::: "memory")
#define CP_WAIT1()  asm volatile("cp.async.wait_group 1;\n" ::: "memory")
#define CP_WAIT0()  asm volatile("cp.async.wait_group 0;\n" ::: "memory")

#define LDSM4(r, addr) \
    asm volatile("ldmatrix.sync.aligned.m8n8.x4.shared.b16 {%0,%1,%2,%3}, [%4];" \
                 : "=r"((r)[0]), "=r"((r)[1]), "=r"((r)[2]), "=r"((r)[3]) : "r"(addr))
#define MMA16816(d, a, b) \
    asm volatile("mma.sync.aligned.m16n8k16.row.col.f32.bf16.bf16.f32 " \
                 "{%0,%1,%2,%3}, {%4,%5,%6,%7}, {%8,%9}, {%0,%1,%2,%3};" \
                 : "+f"((d)[0]), "+f"((d)[1]), "+f"((d)[2]), "+f"((d)[3]) \
                 : "r"((a)[0]), "r"((a)[1]), "r"((a)[2]), "r"((a)[3]), \
                   "r"((b)[0]), "r"((b)[1]))

__device__ __forceinline__ void split2(float v, __nv_bfloat16& h, __nv_bfloat16& l) {
    h = __float2bfloat16_rn(v);
    l = __float2bfloat16_rn(v - __bfloat162float(h));
}

// ============================================================================
// Big split-bf16 GEMM — R9/R6 tiles (128x128, 8 warps 4x2, 32x64 warp tiles,
// 4 stages, regs<=128 for 2 CTA/SM) with PAIR-BARRIER mainloop: one
// WAIT0+barrier per TWO chunks. Safety: at iteration top only groups i,i+1
// are outstanding; issue(i+2)/(i+3) write stages (i-2)&3/(i-1)&3 whose last
// readers compute(i-2)/(i-1) ran before this iteration's barrier.
// ============================================================================
#define MM_STAGES 4
#define MM_ROWB   80
#define MM_ABYTES (128 * MM_ROWB)
#define MM_SSTAGE (2 * MM_ABYTES)
#define MM_SMEM   (MM_STAGES * MM_SSTAGE)   // 81920

__global__ __launch_bounds__(256) void gemm_mma(
    const __nv_bfloat16* __restrict__ Ahi, const __nv_bfloat16* __restrict__ Alo,
    const __nv_bfloat16* __restrict__ Bhi, const __nv_bfloat16* __restrict__ Blo,
    float* __restrict__ C, int M, int N, int K)
{
    extern __shared__ char smem[];
    const int tid  = threadIdx.x;
    const int wid  = tid >> 5;
    const int lane = tid & 31;
    const int m0 = blockIdx.x * 128;
    const int n0 = blockIdx.y * 128;
    const int wm = (wid & 3) * 32;
    const int wn = (wid >> 2) * 64;
    const uint32_t sbase = smem_u32(smem);

    const int KB = K >> 5;
    const int NC = 3 * KB;   // even for K multiples of 64

    float acc[2][8][4];
#pragma unroll
    for (int i = 0; i < 2; i++)
#pragma unroll
        for (int j = 0; j < 8; j++)
#pragma unroll
            for (int t = 0; t < 4; t++) acc[i][j][t] = 0.f;

    const int it0 = tid, it1 = tid + 256;
    const int ar0 = it0 >> 2, ac0 = (it0 & 3) << 4;
    const int ar1 = it1 >> 2, ac1 = (it1 & 3) << 4;

    auto issue = [&](int j) {
        const int s = j & (MM_STAGES - 1);
        const uint32_t As = sbase + s * MM_SSTAGE;
        const uint32_t Bs = As + MM_ABYTES;
        const int seg = j / KB;
        const int kk = j - seg * KB;
        const __nv_bfloat16* Ag = (seg == 1) ? Alo : Ahi;
        const __nv_bfloat16* Bg = (seg == 2) ? Blo : Bhi;
        const size_t kof = (size_t)kk * 32;
        cpa16(As + ar0 * MM_ROWB + ac0, Ag + (size_t)(m0 + ar0) * K + kof + (ac0 >> 1));
        cpa16(As + ar1 * MM_ROWB + ac1, Ag + (size_t)(m0 + ar1) * K + kof + (ac1 >> 1));
        {
            int nn0 = n0 + ar0, nn1 = n0 + ar1;
            int p0 = (nn0 < N) ? 16 : 0;
            int p1 = (nn1 < N) ? 16 : 0;
            if (nn0 >= N) nn0 = 0;
            if (nn1 >= N) nn1 = 0;
            const void* g0 = Bg + (size_t)nn0 * K + kof + (ac0 >> 1);
            const void* g1 = Bg + (size_t)nn1 * K + kof + (ac1 >> 1);
            asm volatile("cp.async.cg.shared.global [%0], [%1], 16, %2;\n"
                         :: "r"(Bs + ar0 * MM_ROWB + ac0), "l"(g0), "r"(p0));
            asm volatile("cp.async.cg.shared.global [%0], [%1], 16, %2;\n"
                         :: "r"(Bs + ar1 * MM_ROWB + ac1), "l"(g1), "r"(p1));
        }
    };

    const int quad = lane >> 3, qj = lane & 7;

    auto compute = [&](int i) {
        const int s = i & (MM_STAGES - 1);
        const uint32_t As = sbase + s * MM_SSTAGE;
        const uint32_t Bs = As + MM_ABYTES;
#pragma unroll
        for (int k16 = 0; k16 < 2; k16++) {
            const int k0 = k16 * 16;
            uint32_t a[2][4];
#pragma unroll
            for (int mt = 0; mt < 2; mt++) {
                int row = wm + mt * 16 + ((quad & 1) ? 8 : 0) + qj;
                int kel = k0 + ((quad & 2) ? 8 : 0);
                LDSM4(a[mt], As + row * MM_ROWB + kel * 2);
            }
            uint32_t b[8][2];
#pragma unroll
            for (int np = 0; np < 4; np++) {
                int row = wn + np * 16 + ((quad & 2) ? 8 : 0) + qj;
                int kel = k0 + ((quad & 1) ? 8 : 0);
                uint32_t t[4];
                LDSM4(t, Bs + row * MM_ROWB + kel * 2);
                b[np * 2][0] = t[0]; b[np * 2][1] = t[1];
                b[np * 2 + 1][0] = t[2]; b[np * 2 + 1][1] = t[3];
            }
#pragma unroll
            for (int mt = 0; mt < 2; mt++)
#pragma unroll
                for (int nt = 0; nt < 8; nt++) MMA16816(acc[mt][nt], a[mt], b[nt]);
        }
    };

    issue(0); CP_COMMIT();
    issue(1); CP_COMMIT();
    for (int i = 0; i < NC; i += 2) {
        CP_WAIT0();
        __syncthreads();
        if (i + 2 < NC) {
            issue(i + 2); CP_COMMIT();
            issue(i + 3); CP_COMMIT();
        }
        compute(i);
        compute(i + 1);
    }

    const int g = lane >> 2, t4 = lane & 3;
#pragma unroll
    for (int mt = 0; mt < 2; mt++)
#pragma unroll
        for (int nt = 0; nt < 8; nt++) {
            int m = m0 + wm + mt * 16 + g;
            int n = n0 + wn + nt * 8 + t4 * 2;
            if (n < N) {
                *(float2*)(C + (size_t)m * N + n) = make_float2(acc[mt][nt][0], acc[mt][nt][1]);
                *(float2*)(C + (size_t)(m + 8) * N + n) = make_float2(acc[mt][nt][2], acc[mt][nt][3]);
            }
        }
}

// ============================================================================
// fp32 -> bf16 hi/lo split
// ============================================================================
__global__ void cvt_kernel(const float* __restrict__ src, __nv_bfloat16* __restrict__ hi,
                           __nv_bfloat16* __restrict__ lo, int n4) {
    int i = blockIdx.x * blockDim.x + threadIdx.x;
    if (i >= n4) return;
    float4 v = ((const float4*)src)[i];
    __nv_bfloat16 h0, h1, h2, h3, l0, l1, l2, l3;
    split2(v.x, h0, l0); split2(v.y, h1, l1);
    split2(v.z, h2, l2); split2(v.w, h3, l3);
    ((__nv_bfloat162*)hi)[2 * i]     = __nv_bfloat162(h0, h1);
    ((__nv_bfloat162*)hi)[2 * i + 1] = __nv_bfloat162(h2, h3);
    ((__nv_bfloat162*)lo)[2 * i]     = __nv_bfloat162(l0, l1);
    ((__nv_bfloat162*)lo)[2 * i + 1] = __nv_bfloat162(l2, l3);
}

// ============================================================================
// dt(softplus) + within-chunk cumsum: one WARP per (c,h), shfl inclusive scan
// ============================================================================
__global__ void dtacs_kernel(const float* __restrict__ dt_bias, const float* __restrict__ A_log) {
    int pair = blockIdx.x * 8 + (threadIdx.x >> 5);   // 0..1023 = c*64+h
    if (pair >= NCH * HH) return;
    int h = pair & 63, c = pair >> 6;
    int lane = threadIdx.x & 31;
    float Ah = -expf(A_log[h]);
    float bias = dt_bias[h];
    float carry = 0.f;
#pragma unroll
    for (int i = 0; i < 8; i++) {
        int l = c * CSZ + i * 32 + lane;
        float v = d_proj[(size_t)l * PROJ_ + INTER_ + CONVDIM_ + h] + bias;
        float sp = (v > 20.f) ? v : log1pf(expf(v));
        d_dt[(size_t)l * HH + h] = sp;
        float x = sp * Ah;
#pragma unroll
        for (int o = 1; o < 32; o <<= 1) {
            float y = __shfl_up_sync(0xffffffffu, x, o);
            if (lane >= o) x += y;
        }
        x += carry;
        d_Acs[(size_t)h * LL + l] = x;
        carry = __shfl_sync(0xffffffffu, x, 31);
    }
}

// conv + silu with 4-l register reuse; inline B/C splits; skip dead fp32 C store
__global__ void conv_kernel(const float* __restrict__ conv_w, const float* __restrict__ conv_b) {
    int cc = blockIdx.x * blockDim.x + threadIdx.x;   // channel
    if (cc >= CONVDIM_) return;
    int l0 = blockIdx.y * 4;
    float w0 = conv_w[cc * 4 + 0], w1 = conv_w[cc * 4 + 1];
    float w2 = conv_w[cc * 4 + 2], w3 = conv_w[cc * 4 + 3];
    float bias = conv_b[cc];
    float x[7];
#pragma unroll
    for (int i = 0; i < 7; i++) {
        int li = l0 - 3 + i;
        x[i] = (li >= 0) ? d_proj[(size_t)li * PROJ_ + INTER_ + cc] : 0.f;
    }
#pragma unroll
    for (int j = 0; j < 4; j++) {
        float a = bias + w0 * x[j] + w1 * x[j + 1] + w2 * x[j + 2] + w3 * x[j + 3];
        float v = a / (1.f + __expf(-a));
        int l = l0 + j;
        if (cc < INTER_ + 1024) d_conv[(size_t)l * CONVDIM_ + cc] = v;
        if (cc >= INTER_) {
            int jj = cc - INTER_;
            __nv_bfloat16 h, lo;
            split2(v, h, lo);
            if (jj < 1024) { d_Bhi[(size_t)l * 1024 + jj] = h; d_Blo[(size_t)l * 1024 + jj] = lo; }
            else { d_Chi2[(size_t)l * 1024 + jj - 1024] = h; d_Clo2[(size_t)l * 1024 + jj - 1024] = lo; }
        }
    }
}

// B^T hi/lo [g*128+n][l]
__global__ void btrans_kernel() {
    __shared__ float tile[32][33];
    int x = blockIdx.x * 32 + threadIdx.x;   // gn
    int y0 = blockIdx.y * 32;                // l
    for (int j = threadIdx.y; j < 32; j += 8)
        tile[j][threadIdx.x] = d_conv[(size_t)(y0 + j) * CONVDIM_ + INTER_ + x];
    __syncthreads();
    int l = y0 + threadIdx.x;
    for (int j = threadIdx.y; j < 32; j += 8) {
        int gn = blockIdx.x * 32 + j;
        __nv_bfloat16 h, lo;
        split2(tile[threadIdx.x][j], h, lo);
        d_BThi[(size_t)gn * LL + l] = h;
        d_BTlo[(size_t)gn * LL + l] = lo;
    }
}

// xdt^T and (xdt*decay)^T hi/lo, computing xdt = conv*dt on the fly
__global__ void xtrans_kernel() {
    __shared__ float tile[32][33];
    int x = blockIdx.x * 32 + threadIdx.x;   // hp
    int y0 = blockIdx.y * 32;                // l
    int hload = x >> 6;
    for (int j = threadIdx.y; j < 32; j += 8)
        tile[j][threadIdx.x] = d_conv[(size_t)(y0 + j) * CONVDIM_ + x] *
                               d_dt[(size_t)(y0 + j) * HH + hload];
    __syncthreads();
    int l = y0 + threadIdx.x;
    int lastl = l | (CSZ - 1);
    for (int j = threadIdx.y; j < 32; j += 8) {
        int hp = blockIdx.x * 32 + j;
        int h = hp >> 6;
        float v = tile[threadIdx.x][j];
        __nv_bfloat16 hh, ll;
        split2(v, hh, ll);
        d_xThi[(size_t)hp * LL + l] = hh;
        d_xTlo[(size_t)hp * LL + l] = ll;
        float dec = __expf(d_Acs[(size_t)h * LL + lastl] - d_Acs[(size_t)h * LL + l]);
        split2(v * dec, hh, ll);
        d_xdThi[(size_t)hp * LL + l] = hh;
        d_xdTlo[(size_t)hp * LL + l] = ll;
    }
}

// inter-chunk recurrence; writes prev splits directly
__global__ void state_scan_kernel() {
    int t = blockIdx.x * blockDim.x + threadIdx.x;
    if (t >= HH * PP * NST) return;
    int n = t & 127, p = (t >> 7) & 63, h = t >> 13;
    float prev = 0.f;
#pragma unroll
    for (int c = 0; c < NCH; c++) {
        size_t idx = ((size_t)(c * HH + h) * PP + p) * NST + n;
        __nv_bfloat16 hh, ll;
        split2(prev, hh, ll);
        d_pvhi[idx] = hh;
        d_pvlo[idx] = ll;
        float cd = __expf(d_Acs[(size_t)h * LL + c * CSZ + 255]);
        prev = prev * cd + d_states[idx];
    }
}

// ============================================================================
// Fused scores + Y_diag + Y_off + D*x kernel (R11 proven version, no skip)
// ============================================================================
#define CK_ROWB 80
#define CK_STAGE (4 * 128 * CK_ROWB)
#define CK_SROW 272
#define CK_SOFF (2 * CK_STAGE)
#define CK_SBYT (128 * CK_SROW)
#define CK_XOFF (CK_SOFF + 2 * CK_SBYT)
#define CK_XBYT (64 * CK_SROW)
#define CK_PVOFF (CK_XOFF + 2 * CK_XBYT)   // 186368
#define CK_PVBYT (64 * CK_SROW)            // 17408
#define CK_SMEM (CK_PVOFF + 2 * CK_PVBYT)  // 221184

__global__ __launch_bounds__(256) void chunk_kernel(const float* __restrict__ Dvec) {
    const int lhalf = blockIdx.x;
    const int z = blockIdx.y;
    const int c = z >> 6, h = z & 63, g = h >> 3;
    extern __shared__ char sm[];
    const uint32_t sb = smem_u32(sm);
    const int tid = threadIdx.x;
    const int wid = tid >> 5, lane = tid & 31;
    const int quad = lane >> 3, qj = lane & 7;
    const int wy = wid & 3, wx = wid >> 2;
    const int l0 = c * CSZ + lhalf * 128;

    float yacc[2][4][4];
    float yoacc[2][4][4];
#pragma unroll
    for (int i = 0; i < 2; i++)
#pragma unroll
        for (int j = 0; j < 4; j++)
#pragma unroll
            for (int t = 0; t < 4; t++) { yacc[i][j][t] = 0.f; yoacc[i][j][t] = 0.f; }

    const float* acsH = d_Acs + (size_t)h * LL + c * CSZ;

    // preload prev[p][n] tile (64 x 128, hi/lo)
#pragma unroll
    for (int rep = 0; rep < 4; rep++) {
        int slot = tid + rep * 256;
        int row = slot >> 4, c16 = (slot & 15) * 16;
        size_t off = (size_t)z * 8192 + row * 128 + (c16 >> 1);
        cpa16(sb + CK_PVOFF + row * CK_SROW + c16, d_pvhi + off);
        cpa16(sb + CK_PVOFF + CK_PVBYT + row * CK_SROW + c16, d_pvlo + off);
    }

    for (int sh = 0; sh <= lhalf; sh++) {
        const int s0 = c * CSZ + sh * 128;
        float acc[2][8][4];
#pragma unroll
        for (int i = 0; i < 2; i++)
#pragma unroll
            for (int j = 0; j < 8; j++)
#pragma unroll
                for (int t = 0; t < 4; t++) acc[i][j][t] = 0.f;

#pragma unroll
        for (int rep = 0; rep < 4; rep++) {
            int slot = tid + rep * 256;
            int row = slot >> 4, c16 = (slot & 15) * 16;
            size_t off = (size_t)(h * 64 + row) * LL + s0 + (c16 >> 1);
            cpa16(sb + CK_XOFF + row * CK_SROW + c16, d_xThi + off);
            cpa16(sb + CK_XOFF + CK_XBYT + row * CK_SROW + c16, d_xTlo + off);
        }
        {
            const uint32_t base = sb + 0 * CK_STAGE;
#pragma unroll
            for (int rep = 0; rep < 2; rep++) {
                int slot = tid + rep * 256;
                int row = slot >> 2, c16 = (slot & 3) * 16;
                int kofe = 0 * 32 + (c16 >> 1);
                size_t crow = (size_t)(l0 + row) * 1024 + g * 128 + kofe;
                size_t brow = (size_t)(s0 + row) * 1024 + g * 128 + kofe;
                cpa16(base + row * CK_ROWB + c16, d_Chi2 + crow);
                cpa16(base + 10240 + row * CK_ROWB + c16, d_Clo2 + crow);
                cpa16(base + 20480 + row * CK_ROWB + c16, d_Bhi + brow);
                cpa16(base + 30720 + row * CK_ROWB + c16, d_Blo + brow);
            }
        }
        CP_COMMIT();
        {
            const uint32_t base = sb + 1 * CK_STAGE;
#pragma unroll
            for (int rep = 0; rep < 2; rep++) {
                int slot = tid + rep * 256;
                int row = slot >> 2, c16 = (slot & 3) * 16;
                int kofe = 1 * 32 + (c16 >> 1);
                size_t crow = (size_t)(l0 + row) * 1024 + g * 128 + kofe;
                size_t brow = (size_t)(s0 + row) * 1024 + g * 128 + kofe;
                cpa16(base + row * CK_ROWB + c16, d_Chi2 + crow);
                cpa16(base + 10240 + row * CK_ROWB + c16, d_Clo2 + crow);
                cpa16(base + 20480 + row * CK_ROWB + c16, d_Bhi + brow);
                cpa16(base + 30720 + row * CK_ROWB + c16, d_Blo + brow);
            }
        }
        CP_COMMIT();

        for (int kc = 0; kc < 4; kc++) {
            if (kc == 3) CP_WAIT0(); else CP_WAIT1();
            __syncthreads();
            {
                const uint32_t base = sb + (kc & 1) * CK_STAGE;
                const uint32_t Ch = base, Cl = base + 10240, Bh = base + 20480, Bl = base + 30720;
                const uint32_t Ph = sb + CK_PVOFF, Pl = sb + CK_PVOFF + CK_PVBYT;
#pragma unroll
                for (int k16 = 0; k16 < 2; k16++) {
                    const int k0 = k16 * 16;
                    uint32_t ah[2][4], al_[2][4];
#pragma unroll
                    for (int mt = 0; mt < 2; mt++) {
                        int row = wy * 32 + mt * 16 + ((quad & 1) ? 8 : 0) + qj;
                        int kel = k0 + ((quad & 2) ? 8 : 0);
                        LDSM4(ah[mt], Ch + row * CK_ROWB + kel * 2);
                        LDSM4(al_[mt], Cl + row * CK_ROWB + kel * 2);
                    }
                    uint32_t bh[8][2], bl[8][2];
#pragma unroll
                    for (int np = 0; np < 4; np++) {
                        int row = wx * 64 + np * 16 + ((quad & 2) ? 8 : 0) + qj;
                        int kel = k0 + ((quad & 1) ? 8 : 0);
                        uint32_t t[4];
                        LDSM4(t, Bh + row * CK_ROWB + kel * 2);
                        bh[np * 2][0] = t[0]; bh[np * 2][1] = t[1];
                        bh[np * 2 + 1][0] = t[2]; bh[np * 2 + 1][1] = t[3];
                        LDSM4(t, Bl + row * CK_ROWB + kel * 2);
                        bl[np * 2][0] = t[0]; bl[np * 2][1] = t[1];
                        bl[np * 2 + 1][0] = t[2]; bl[np * 2 + 1][1] = t[3];
                    }
#pragma unroll
                    for (int mt = 0; mt < 2; mt++)
#pragma unroll
                        for (int nt = 0; nt < 8; nt++) {
                            MMA16816(acc[mt][nt], ah[mt], bh[nt]);
                            MMA16816(acc[mt][nt], al_[mt], bh[nt]);
                            MMA16816(acc[mt][nt], ah[mt], bl[nt]);
                        }
                    // ---- fused Y_off: C fragments vs prev tile (once per block)
                    if (sh == 0) {
                        uint32_t ph[4][2], pl[4][2];
#pragma unroll
                        for (int np = 0; np < 2; np++) {
                            int row = wx * 32 + np * 16 + ((quad & 2) ? 8 : 0) + qj;
                            int kel = kc * 32 + k0 + ((quad & 1) ? 8 : 0);
                            uint32_t t[4];
                            LDSM4(t, Ph + row * CK_SROW + kel * 2);
                            ph[np * 2][0] = t[0]; ph[np * 2][1] = t[1];
                            ph[np * 2 + 1][0] = t[2]; ph[np * 2 + 1][1] = t[3];
                            LDSM4(t, Pl + row * CK_SROW + kel * 2);
                            pl[np * 2][0] = t[0]; pl[np * 2][1] = t[1];
                            pl[np * 2 + 1][0] = t[2]; pl[np * 2 + 1][1] = t[3];
                        }
#pragma unroll
                        for (int mt = 0; mt < 2; mt++)
#pragma unroll
                            for (int nt = 0; nt < 4; nt++) {
                                MMA16816(yoacc[mt][nt], ah[mt], ph[nt]);
                                MMA16816(yoacc[mt][nt], al_[mt], ph[nt]);
                                MMA16816(yoacc[mt][nt], ah[mt], pl[nt]);
                            }
                    }
                }
            }
            __syncthreads();
            if (kc + 2 < 4) {
                const uint32_t base = sb + ((kc + 2) & 1) * CK_STAGE;
#pragma unroll
                for (int rep = 0; rep < 2; rep++) {
                    int slot = tid + rep * 256;
                    int row = slot >> 2, c16 = (slot & 3) * 16;
                    int kofe = (kc + 2) * 32 + (c16 >> 1);
                    size_t crow = (size_t)(l0 + row) * 1024 + g * 128 + kofe;
                    size_t brow = (size_t)(s0 + row) * 1024 + g * 128 + kofe;
                    cpa16(base + row * CK_ROWB + c16, d_Chi2 + crow);
                    cpa16(base + 10240 + row * CK_ROWB + c16, d_Clo2 + crow);
                    cpa16(base + 20480 + row * CK_ROWB + c16, d_Bhi + brow);
                    cpa16(base + 30720 + row * CK_ROWB + c16, d_Blo + brow);
                }
                CP_COMMIT();
            }
        }

        {
            const bool diag = (sh == lhalf);
            char* Sh = sm + CK_SOFF;
            char* Sl = sm + CK_SOFF + CK_SBYT;
#pragma unroll
            for (int mt = 0; mt < 2; mt++) {
                int r0 = wy * 32 + mt * 16 + (lane >> 2);
#pragma unroll
                for (int half = 0; half < 2; half++) {
                    int r = r0 + half * 8;
                    float al = acsH[lhalf * 128 + r];
#pragma unroll
                    for (int nt = 0; nt < 8; nt++) {
                        int cc = wx * 64 + nt * 8 + (lane & 3) * 2;
                        float v0 = acc[mt][nt][half * 2 + 0];
                        float v1 = acc[mt][nt][half * 2 + 1];
                        float as0 = acsH[sh * 128 + cc];
                        float as1 = acsH[sh * 128 + cc + 1];
                        v0 = (!diag || (cc <= r)) ? v0 * __expf(al - as0) : 0.f;
                        v1 = (!diag || (cc + 1 <= r)) ? v1 * __expf(al - as1) : 0.f;
                        __nv_bfloat16 h0, h1, q0, q1;
                        split2(v0, h0, q0);
                        split2(v1, h1, q1);
                        *(__nv_bfloat162*)(Sh + r * CK_SROW + cc * 2) = __nv_bfloat162(h0, h1);
                        *(__nv_bfloat162*)(Sl + r * CK_SROW + cc * 2) = __nv_bfloat162(q0, q1);
                    }
                }
            }
        }
        __syncthreads();

        {
            const uint32_t Sh = sb + CK_SOFF, Sl = sb + CK_SOFF + CK_SBYT;
            const uint32_t Xh = sb + CK_XOFF, Xl = sb + CK_XOFF + CK_XBYT;
#pragma unroll 2
            for (int k16 = 0; k16 < 8; k16++) {
                const int k0 = k16 * 16;
                uint32_t ah[2][4], al_[2][4];
#pragma unroll
                for (int mt = 0; mt < 2; mt++) {
                    int row = wy * 32 + mt * 16 + ((quad & 1) ? 8 : 0) + qj;
                    int kel = k0 + ((quad & 2) ? 8 : 0);
                    LDSM4(ah[mt], Sh + row * CK_SROW + kel * 2);
                    LDSM4(al_[mt], Sl + row * CK_SROW + kel * 2);
                }
                uint32_t bh[4][2], bl[4][2];
#pragma unroll
                for (int np = 0; np < 2; np++) {
                    int row = wx * 32 + np * 16 + ((quad & 2) ? 8 : 0) + qj;
                    int kel = k0 + ((quad & 1) ? 8 : 0);
                    uint32_t t[4];
                    LDSM4(t, Xh + row * CK_SROW + kel * 2);
                    bh[np * 2][0] = t[0]; bh[np * 2][1] = t[1];
                    bh[np * 2 + 1][0] = t[2]; bh[np * 2 + 1][1] = t[3];
                    LDSM4(t, Xl + row * CK_SROW + kel * 2);
                    bl[np * 2][0] = t[0]; bl[np * 2][1] = t[1];
                    bl[np * 2 + 1][0] = t[2]; bl[np * 2 + 1][1] = t[3];
                }
#pragma unroll
                for (int mt = 0; mt < 2; mt++)
#pragma unroll
                    for (int nt = 0; nt < 4; nt++) {
                        MMA16816(yacc[mt][nt], ah[mt], bh[nt]);
                        MMA16816(yacc[mt][nt], al_[mt], bh[nt]);
                        MMA16816(yacc[mt][nt], ah[mt], bl[nt]);
                    }
            }
        }
        __syncthreads();
    }

    // ---- merged epilogue: Y = Y_diag + exp(Acs)*Y_off + D*x
    const float Dv = Dvec[h];
#pragma unroll
    for (int mt = 0; mt < 2; mt++)
#pragma unroll
        for (int nt = 0; nt < 4; nt++) {
            int r = wy * 32 + mt * 16 + (lane >> 2);
            int p = wx * 32 + nt * 8 + (lane & 3) * 2;
#pragma unroll
            for (int half = 0; half < 2; half++) {
                int rr = r + half * 8;
                int gl = l0 + rr;
                float sd = __expf(acsH[lhalf * 128 + rr]);
                float2 x = *(float2*)(d_conv + (size_t)gl * CONVDIM_ + h * 64 + p);
                float y0 = yacc[mt][nt][half * 2 + 0] + yoacc[mt][nt][half * 2 + 0] * sd + Dv * x.x;
                float y1 = yacc[mt][nt][half * 2 + 1] + yoacc[mt][nt][half * 2 + 1] * sd + Dv * x.y;
                *(float2*)(d_Y + (size_t)gl * INTER_ + h * 64 + p) = make_float2(y0, y1);
            }
        }
}

// ============================================================================
// states kernel
// ============================================================================
#define ST_STRIDE 30720
#define ST_SMEM   (2 * ST_STRIDE)

__global__ __launch_bounds__(256) void states_mma_kernel() {
    const int z = blockIdx.x;
    const int c = z >> 6, h = z & 63, g = h >> 3;
    extern __shared__ char sm[];
    const uint32_t sb = smem_u32(sm);
    const int tid = threadIdx.x;
    const int wid = tid >> 5, lane = tid & 31;
    const int quad = lane >> 3, qj = lane & 7;
    const int wy = wid & 1, wx = wid >> 1;

    float acc[2][4][4];
#pragma unroll
    for (int i = 0; i < 2; i++)
#pragma unroll
        for (int j = 0; j < 4; j++)
#pragma unroll
            for (int t = 0; t < 4; t++) acc[i][j][t] = 0.f;

    auto issue = [&](int kc) {
        const uint32_t base = sb + (kc & 1) * ST_STRIDE;
        {
            int slot = tid;
            int row = slot >> 2, c16 = (slot & 3) * 16;
            size_t off = (size_t)(h * 64 + row) * LL + c * CSZ + kc * 32 + (c16 >> 1);
            cpa16(base + row * 80 + c16, d_xdThi + off);
            cpa16(base + 5120 + row * 80 + c16, d_xdTlo + off);
        }
#pragma unroll
        for (int rep = 0; rep < 2; rep++) {
            int slot = tid + rep * 256;
            int row = slot >> 2, c16 = (slot & 3) * 16;
            size_t off = (size_t)(g * 128 + row) * LL + c * CSZ + kc * 32 + (c16 >> 1);
            cpa16(base + 10240 + row * 80 + c16, d_BThi + off);
            cpa16(base + 20480 + row * 80 + c16, d_BTlo + off);
        }
    };

    issue(0); CP_COMMIT();
    issue(1); CP_COMMIT();
    for (int kc = 0; kc < 8; kc++) {
        if (kc == 7) CP_WAIT0(); else CP_WAIT1();
        __syncthreads();
        {
            const uint32_t base = sb + (kc & 1) * ST_STRIDE;
            const uint32_t Ah = base, Al = base + 5120, Bh = base + 10240, Bl = base + 20480;
#pragma unroll
            for (int k16 = 0; k16 < 2; k16++) {
                const int k0 = k16 * 16;
                uint32_t ah[2][4], al_[2][4];
#pragma unroll
                for (int mt = 0; mt < 2; mt++) {
                    int row = wy * 32 + mt * 16 + ((quad & 1) ? 8 : 0) + qj;
                    int kel = k0 + ((quad & 2) ? 8 : 0);
                    LDSM4(ah[mt], Ah + row * 80 + kel * 2);
                    LDSM4(al_[mt], Al + row * 80 + kel * 2);
                }
                uint32_t bh[4][2], bl[4][2];
#pragma unroll
                for (int np = 0; np < 2; np++) {
                    int row = wx * 32 + np * 16 + ((quad & 2) ? 8 : 0) + qj;
                    int kel = k0 + ((quad & 1) ? 8 : 0);
                    uint32_t t[4];
                    LDSM4(t, Bh + row * 80 + kel * 2);
                    bh[np * 2][0] = t[0]; bh[np * 2][1] = t[1];
                    bh[np * 2 + 1][0] = t[2]; bh[np * 2 + 1][1] = t[3];
                    LDSM4(t, Bl + row * 80 + kel * 2);
                    bl[np * 2][0] = t[0]; bl[np * 2][1] = t[1];
                    bl[np * 2 + 1][0] = t[2]; bl[np * 2 + 1][1] = t[3];
                }
#pragma unroll
                for (int mt = 0; mt < 2; mt++)
#pragma unroll
                    for (int nt = 0; nt < 4; nt++) {
                        MMA16816(acc[mt][nt], ah[mt], bh[nt]);
                        MMA16816(acc[mt][nt], al_[mt], bh[nt]);
                        MMA16816(acc[mt][nt], ah[mt], bl[nt]);
                    }
            }
        }
        __syncthreads();
        if (kc + 2 < 8) { issue(kc + 2); CP_COMMIT(); }
    }

#pragma unroll
    for (int mt = 0; mt < 2; mt++)
#pragma unroll
        for (int nt = 0; nt < 4; nt++) {
            int p = wy * 32 + mt * 16 + (lane >> 2);
            int n = wx * 32 + nt * 8 + (lane & 3) * 2;
            *(float2*)(d_states + (size_t)z * 8192 + p * 128 + n) =
                make_float2(acc[mt][nt][0], acc[mt][nt][1]);
            *(float2*)(d_states + (size_t)z * 8192 + (p + 8) * 128 + n) =
                make_float2(acc[mt][nt][2], acc[mt][nt][3]);
        }
}

// ============================================================================
// gated group RMS norm — writes GEMM2 A-operand splits directly
// ============================================================================
__global__ __launch_bounds__(256) void norm_kernel(const float* __restrict__ norm_weight) {
    __shared__ float gbuf[INTER_];
    __shared__ float rs[GG];
    int l = blockIdx.x, tid = threadIdx.x;
    for (int i = tid; i < INTER_; i += 256) {
        float y = d_Y[(size_t)l * INTER_ + i];
        float gt = d_proj[(size_t)l * PROJ_ + i];
        float sg = 1.f / (1.f + __expf(-gt));
        gbuf[i] = y * gt * sg;
    }
    __syncthreads();
    int w = tid >> 5, lane = tid & 31;
    float ss = 0.f;
    for (int j = lane; j < 512; j += 32) { float v = gbuf[w * 512 + j]; ss += v * v; }
#pragma unroll
    for (int o = 16; o > 0; o >>= 1) ss += __shfl_xor_sync(0xffffffffu, ss, o);
    if (lane == 0) rs[w] = rsqrtf(ss * (1.f / 512.f) + 1e-5f);
    __syncthreads();
    for (int i = tid; i < INTER_; i += 256) {
        float v = gbuf[i] * rs[i >> 9] * norm_weight[i];
        __nv_bfloat16 h, lo;
        split2(v, h, lo);
        d_A2hi[(size_t)l * INTER_ + i] = h;
        d_A2lo[(size_t)l * INTER_ + i] = lo;
    }
}

// ============================================================================
extern "C" void kernel_launch(void* const* d_in, const int* in_sizes, int n_in,
                              void* d_out, int out_size) {
    (void)in_sizes; (void)n_in; (void)out_size;
    const float* hidden      = (const float*)d_in[0];
    const float* W_in        = (const float*)d_in[1];
    const float* conv_w      = (const float*)d_in[2];
    const float* conv_b      = (const float*)d_in[3];
    const float* dt_bias     = (const float*)d_in[4];
    const float* A_log       = (const float*)d_in[5];
    const float* Dvec        = (const float*)d_in[6];
    const float* norm_weight = (const float*)d_in[7];
    const float* W_out       = (const float*)d_in[8];
    float* out = (float*)d_out;

    float *p_proj = nullptr;
    __nv_bfloat16 *pA1h, *pA1l, *pW1h, *pW1l, *pA2h, *pA2l, *pW2h, *pW2l;
    cudaGetSymbolAddress((void**)&p_proj, d_proj);
    cudaGetSymbolAddress((void**)&pA1h, d_A1hi);
    cudaGetSymbolAddress((void**)&pA1l, d_A1lo);
    cudaGetSymbolAddress((void**)&pW1h, d_W1hi);
    cudaGetSymbolAddress((void**)&pW1l, d_W1lo);
    cudaGetSymbolAddress((void**)&pA2h, d_A2hi);
    cudaGetSymbolAddress((void**)&pA2l, d_A2lo);
    cudaGetSymbolAddress((void**)&pW2h, d_W2hi);
    cudaGetSymbolAddress((void**)&pW2l, d_W2lo);

    cudaFuncSetAttribute(gemm_mma, cudaFuncAttributeMaxDynamicSharedMemorySize, MM_SMEM);
    cudaFuncSetAttribute(chunk_kernel, cudaFuncAttributeMaxDynamicSharedMemorySize, CK_SMEM);
    cudaFuncSetAttribute(states_mma_kernel, cudaFuncAttributeMaxDynamicSharedMemorySize, ST_SMEM);

    // 0) splits for big GEMM operands
    { int n4 = (LL * DMODEL) / 4;    cvt_kernel<<<(n4 + 255) / 256, 256>>>(hidden, pA1h, pA1l, n4); }
    { int n4 = (PROJ_ * DMODEL) / 4; cvt_kernel<<<(n4 + 255) / 256, 256>>>(W_in, pW1h, pW1l, n4); }
    { int n4 = (DMODEL * INTER_) / 4; cvt_kernel<<<(n4 + 255) / 256, 256>>>(W_out, pW2h, pW2l, n4); }
    // 1) input projection
    {
        dim3 grid(LL / 128, (PROJ_ + 127) / 128);
        gemm_mma<<<grid, 256, MM_SMEM>>>(pA1h, pA1l, pW1h, pW1l, p_proj, LL, PROJ_, DMODEL);
    }
    // 2-3) dt + cumsum (warp-scan), conv(+BC splits)
    dtacs_kernel<<<NCH * HH / 8, 256>>>(dt_bias, A_log);
    {
        dim3 grid(CONVDIM_ / 256, LL / 4);
        conv_kernel<<<grid, 256>>>(conv_w, conv_b);
    }
    // 4) transposed operand prep
    { dim3 grid(1024 / 32, LL / 32); btrans_kernel<<<grid, dim3(32, 8)>>>(); }
    { dim3 grid(INTER_ / 32, LL / 32); xtrans_kernel<<<grid, dim3(32, 8)>>>(); }
    // 5) states + scan (produces prev splits needed by fused chunk)
    states_mma_kernel<<<NBATCH, 256, ST_SMEM>>>();
    state_scan_kernel<<<(HH * PP * NST) / 256, 256>>>();
    // 6) fused scores + Y_diag + Y_off + D*x
    chunk_kernel<<<dim3(2, NBATCH), 256, CK_SMEM>>>(Dvec);
    // 7) norm (+A2 splits)
    norm_kernel<<<LL, 256>>>(norm_weight);
    // 8) output projection
    {
        dim3 grid(LL / 128, DMODEL / 128);
        gemm_mma<<<grid, 256, MM_SMEM>>>(pA2h, pA2l, pW2h, pW2l, out, LL, DMODEL, INTER_);
    }
}

// round 17
// speedup vs baseline: 1.0753x; 1.0753x over previous
#include <cuda_runtime.h>
#include <cuda_bf16.h>
#include <math.h>
#include <stdint.h>

// ---------------- problem constants ----------------
#define HH      64
#define PP      64
#define NST     128
#define GG      8
#define DMODEL  2048
#define CSZ     256
#define LL      4096
#define INTER_  4096
#define CONVDIM_ 6144
#define PROJ_   10304
#define NCH     16
#define NBATCH  1024

// ---------------- fp32 scratch ----------------
__device__ float d_proj[(size_t)LL * PROJ_];
__device__ float d_conv[(size_t)LL * CONVDIM_];
__device__ float d_dt[(size_t)LL * HH];
__device__ float d_Acs[(size_t)HH * LL];
__device__ float d_states[(size_t)NBATCH * PP * NST];
__device__ float d_Y[(size_t)LL * INTER_];

// ---------------- bf16 hi/lo operand arrays ----------------
__device__ __nv_bfloat16 d_A1hi[(size_t)LL * DMODEL];
__device__ __nv_bfloat16 d_A1lo[(size_t)LL * DMODEL];
__device__ __nv_bfloat16 d_W1hi[(size_t)PROJ_ * DMODEL];
__device__ __nv_bfloat16 d_W1lo[(size_t)PROJ_ * DMODEL];
__device__ __nv_bfloat16 d_A2hi[(size_t)LL * INTER_];
__device__ __nv_bfloat16 d_A2lo[(size_t)LL * INTER_];
__device__ __nv_bfloat16 d_W2hi[(size_t)DMODEL * INTER_];
__device__ __nv_bfloat16 d_W2lo[(size_t)DMODEL * INTER_];

__device__ __nv_bfloat16 d_Bhi[(size_t)LL * 1024];   // B  [l][g*128+n]
__device__ __nv_bfloat16 d_Blo[(size_t)LL * 1024];
__device__ __nv_bfloat16 d_Chi2[(size_t)LL * 1024];  // C  [l][g*128+n]
__device__ __nv_bfloat16 d_Clo2[(size_t)LL * 1024];
__device__ __nv_bfloat16 d_BThi[(size_t)1024 * LL];  // B^T [g*128+n][l]
__device__ __nv_bfloat16 d_BTlo[(size_t)1024 * LL];
__device__ __nv_bfloat16 d_xThi[(size_t)INTER_ * LL];   // xdt^T   [h*64+p][l]
__device__ __nv_bfloat16 d_xTlo[(size_t)INTER_ * LL];
__device__ __nv_bfloat16 d_xdThi[(size_t)INTER_ * LL];  // (xdt*decay)^T
__device__ __nv_bfloat16 d_xdTlo[(size_t)INTER_ * LL];
__device__ __nv_bfloat16 d_pvhi[(size_t)NBATCH * PP * NST]; // prev [z][p][n]
__device__ __nv_bfloat16 d_pvlo[(size_t)NBATCH * PP * NST];

// ---------------- helpers ----------------
__device__ __forceinline__ uint32_t smem_u32(const void* p) {
    uint32_t a;
    asm("{ .reg .u64 t; cvta.to.shared.u64 t, %1; cvt.u32.u64 %0, t; }" : "=r"(a) : "l"(p));
    return a;
}
__device__ __forceinline__ void cpa16(uint32_t dst, const void* src) {
    asm volatile("cp.async.cg.shared.global [%0], [%1], 16;\n" :: "r"(dst), "l"(src));
}
#define CP_COMMIT() asm volatile("cp.async.commit_group;\n" ::: "memory")
#define CP_WAIT2()  asm volatile("cp.async.wait_group 2;\n" ::: "memory")
#define CP_WAIT1()  asm volatile("cp.async.wait_group 1;\n" ::: "memory")
#define CP_WAIT0()  asm volatile("cp.async.wait_group 0;\n" ::: "memory")

#define LDSM4(r, addr) \
    asm volatile("ldmatrix.sync.aligned.m8n8.x4.shared.b16 {%0,%1,%2,%3}, [%4];" \
                 : "=r"((r)[0]), "=r"((r)[1]), "=r"((r)[2]), "=r"((r)[3]) : "r"(addr))
#define MMA16816(d, a, b) \
    asm volatile("mma.sync.aligned.m16n8k16.row.col.f32.bf16.bf16.f32 " \
                 "{%0,%1,%2,%3}, {%4,%5,%6,%7}, {%8,%9}, {%0,%1,%2,%3};" \
                 : "+f"((d)[0]), "+f"((d)[1]), "+f"((d)[2]), "+f"((d)[3]) \
                 : "r"((a)[0]), "r"((a)[1]), "r"((a)[2]), "r"((a)[3]), \
                   "r"((b)[0]), "r"((b)[1]))

__device__ __forceinline__ void split2(float v, __nv_bfloat16& h, __nv_bfloat16& l) {
    h = __float2bfloat16_rn(v);
    l = __float2bfloat16_rn(v - __bfloat162float(h));
}

// ============================================================================
// Big split-bf16 GEMM — EXACT R9/R6 configuration (proven best; FROZEN:
// R7/R8/R10/R15 perturbations all regressed)
// ============================================================================
#define MM_STAGES 4
#define MM_ROWB   80
#define MM_ABYTES (128 * MM_ROWB)
#define MM_SSTAGE (2 * MM_ABYTES)
#define MM_SMEM   (MM_STAGES * MM_SSTAGE)   // 81920

__global__ __launch_bounds__(256) void gemm_mma(
    const __nv_bfloat16* __restrict__ Ahi, const __nv_bfloat16* __restrict__ Alo,
    const __nv_bfloat16* __restrict__ Bhi, const __nv_bfloat16* __restrict__ Blo,
    float* __restrict__ C, int M, int N, int K)
{
    extern __shared__ char smem[];
    const int tid  = threadIdx.x;
    const int wid  = tid >> 5;
    const int lane = tid & 31;
    const int m0 = blockIdx.x * 128;
    const int n0 = blockIdx.y * 128;
    const int wm = (wid & 3) * 32;
    const int wn = (wid >> 2) * 64;
    const uint32_t sbase = smem_u32(smem);

    const int KB = K >> 5;
    const int NC = 3 * KB;

    float acc[2][8][4];
#pragma unroll
    for (int i = 0; i < 2; i++)
#pragma unroll
        for (int j = 0; j < 8; j++)
#pragma unroll
            for (int t = 0; t < 4; t++) acc[i][j][t] = 0.f;

    const int it0 = tid, it1 = tid + 256;
    const int ar0 = it0 >> 2, ac0 = (it0 & 3) << 4;
    const int ar1 = it1 >> 2, ac1 = (it1 & 3) << 4;

    auto issue = [&](int j) {
        const int s = j & (MM_STAGES - 1);
        const uint32_t As = sbase + s * MM_SSTAGE;
        const uint32_t Bs = As + MM_ABYTES;
        const int seg = j / KB;
        const int kk = j - seg * KB;
        const __nv_bfloat16* Ag = (seg == 1) ? Alo : Ahi;
        const __nv_bfloat16* Bg = (seg == 2) ? Blo : Bhi;
        const size_t kof = (size_t)kk * 32;
        cpa16(As + ar0 * MM_ROWB + ac0, Ag + (size_t)(m0 + ar0) * K + kof + (ac0 >> 1));
        cpa16(As + ar1 * MM_ROWB + ac1, Ag + (size_t)(m0 + ar1) * K + kof + (ac1 >> 1));
        {
            int nn0 = n0 + ar0, nn1 = n0 + ar1;
            int p0 = (nn0 < N) ? 16 : 0;
            int p1 = (nn1 < N) ? 16 : 0;
            if (nn0 >= N) nn0 = 0;
            if (nn1 >= N) nn1 = 0;
            const void* g0 = Bg + (size_t)nn0 * K + kof + (ac0 >> 1);
            const void* g1 = Bg + (size_t)nn1 * K + kof + (ac1 >> 1);
            asm volatile("cp.async.cg.shared.global [%0], [%1], 16, %2;\n"
                         :: "r"(Bs + ar0 * MM_ROWB + ac0), "l"(g0), "r"(p0));
            asm volatile("cp.async.cg.shared.global [%0], [%1], 16, %2;\n"
                         :: "r"(Bs + ar1 * MM_ROWB + ac1), "l"(g1), "r"(p1));
        }
    };

    const int quad = lane >> 3, qj = lane & 7;

    auto compute = [&](int i) {
        const int s = i & (MM_STAGES - 1);
        const uint32_t As = sbase + s * MM_SSTAGE;
        const uint32_t Bs = As + MM_ABYTES;
#pragma unroll
        for (int k16 = 0; k16 < 2; k16++) {
            const int k0 = k16 * 16;
            uint32_t a[2][4];
#pragma unroll
            for (int mt = 0; mt < 2; mt++) {
                int row = wm + mt * 16 + ((quad & 1) ? 8 : 0) + qj;
                int kel = k0 + ((quad & 2) ? 8 : 0);
                LDSM4(a[mt], As + row * MM_ROWB + kel * 2);
            }
            uint32_t b[8][2];
#pragma unroll
            for (int np = 0; np < 4; np++) {
                int row = wn + np * 16 + ((quad & 2) ? 8 : 0) + qj;
                int kel = k0 + ((quad & 1) ? 8 : 0);
                uint32_t t[4];
                LDSM4(t, Bs + row * MM_ROWB + kel * 2);
                b[np * 2][0] = t[0]; b[np * 2][1] = t[1];
                b[np * 2 + 1][0] = t[2]; b[np * 2 + 1][1] = t[3];
            }
#pragma unroll
            for (int mt = 0; mt < 2; mt++)
#pragma unroll
                for (int nt = 0; nt < 8; nt++) MMA16816(acc[mt][nt], a[mt], b[nt]);
        }
    };

    issue(0); CP_COMMIT();
    issue(1); CP_COMMIT();
    for (int i = 0; i < NC; i++) {
        if (i + 2 < NC) issue(i + 2);
        CP_COMMIT();
        CP_WAIT2();
        __syncthreads();
        compute(i);
    }

    const int g = lane >> 2, t4 = lane & 3;
#pragma unroll
    for (int mt = 0; mt < 2; mt++)
#pragma unroll
        for (int nt = 0; nt < 8; nt++) {
            int m = m0 + wm + mt * 16 + g;
            int n = n0 + wn + nt * 8 + t4 * 2;
            if (n < N) {
                *(float2*)(C + (size_t)m * N + n) = make_float2(acc[mt][nt][0], acc[mt][nt][1]);
                *(float2*)(C + (size_t)(m + 8) * N + n) = make_float2(acc[mt][nt][2], acc[mt][nt][3]);
            }
        }
}

// ============================================================================
// fp32 -> bf16 hi/lo split
// ============================================================================
__global__ void cvt_kernel(const float* __restrict__ src, __nv_bfloat16* __restrict__ hi,
                           __nv_bfloat16* __restrict__ lo, int n4) {
    int i = blockIdx.x * blockDim.x + threadIdx.x;
    if (i >= n4) return;
    float4 v = ((const float4*)src)[i];
    __nv_bfloat16 h0, h1, h2, h3, l0, l1, l2, l3;
    split2(v.x, h0, l0); split2(v.y, h1, l1);
    split2(v.z, h2, l2); split2(v.w, h3, l3);
    ((__nv_bfloat162*)hi)[2 * i]     = __nv_bfloat162(h0, h1);
    ((__nv_bfloat162*)hi)[2 * i + 1] = __nv_bfloat162(h2, h3);
    ((__nv_bfloat162*)lo)[2 * i]     = __nv_bfloat162(l0, l1);
    ((__nv_bfloat162*)lo)[2 * i + 1] = __nv_bfloat162(l2, l3);
}

// ============================================================================
// dt(softplus) + within-chunk cumsum: one WARP per (c,h), shfl inclusive scan
// ============================================================================
__global__ void dtacs_kernel(const float* __restrict__ dt_bias, const float* __restrict__ A_log) {
    int pair = blockIdx.x * 8 + (threadIdx.x >> 5);   // 0..1023 = c*64+h
    if (pair >= NCH * HH) return;
    int h = pair & 63, c = pair >> 6;
    int lane = threadIdx.x & 31;
    float Ah = -expf(A_log[h]);
    float bias = dt_bias[h];
    float carry = 0.f;
#pragma unroll
    for (int i = 0; i < 8; i++) {
        int l = c * CSZ + i * 32 + lane;
        float v = d_proj[(size_t)l * PROJ_ + INTER_ + CONVDIM_ + h] + bias;
        float sp = (v > 20.f) ? v : log1pf(expf(v));
        d_dt[(size_t)l * HH + h] = sp;
        float x = sp * Ah;
#pragma unroll
        for (int o = 1; o < 32; o <<= 1) {
            float y = __shfl_up_sync(0xffffffffu, x, o);
            if (lane >= o) x += y;
        }
        x += carry;
        d_Acs[(size_t)h * LL + l] = x;
        carry = __shfl_sync(0xffffffffu, x, 31);
    }
}

// conv + silu; fp32 store ONLY for x region (B/C fp32 copies are dead);
// inline B/C bf16 splits
__global__ void conv_kernel(const float* __restrict__ conv_w, const float* __restrict__ conv_b) {
    int cc = blockIdx.x * blockDim.x + threadIdx.x;   // channel
    if (cc >= CONVDIM_) return;
    int l0 = blockIdx.y * 4;
    float w0 = conv_w[cc * 4 + 0], w1 = conv_w[cc * 4 + 1];
    float w2 = conv_w[cc * 4 + 2], w3 = conv_w[cc * 4 + 3];
    float bias = conv_b[cc];
    float x[7];
#pragma unroll
    for (int i = 0; i < 7; i++) {
        int li = l0 - 3 + i;
        x[i] = (li >= 0) ? d_proj[(size_t)li * PROJ_ + INTER_ + cc] : 0.f;
    }
#pragma unroll
    for (int j = 0; j < 4; j++) {
        float a = bias + w0 * x[j] + w1 * x[j + 1] + w2 * x[j + 2] + w3 * x[j + 3];
        float v = a / (1.f + __expf(-a));
        int l = l0 + j;
        if (cc < INTER_) d_conv[(size_t)l * CONVDIM_ + cc] = v;
        if (cc >= INTER_) {
            int jj = cc - INTER_;
            __nv_bfloat16 h, lo;
            split2(v, h, lo);
            if (jj < 1024) { d_Bhi[(size_t)l * 1024 + jj] = h; d_Blo[(size_t)l * 1024 + jj] = lo; }
            else { d_Chi2[(size_t)l * 1024 + jj - 1024] = h; d_Clo2[(size_t)l * 1024 + jj - 1024] = lo; }
        }
    }
}

// B^T hi/lo [g*128+n][l]: pure bf16 transpose of d_Bhi/d_Blo (bit-identical
// to splitting the transposed fp32 values; halves the read traffic)
__global__ void btrans_kernel() {
    __shared__ uint32_t tile[32][33];   // packed (hi<<16)|lo
    int x = blockIdx.x * 32 + threadIdx.x;   // gn
    int y0 = blockIdx.y * 32;                // l
    for (int j = threadIdx.y; j < 32; j += 8) {
        size_t src = (size_t)(y0 + j) * 1024 + x;
        uint16_t hb = __bfloat16_as_ushort(d_Bhi[src]);
        uint16_t lb = __bfloat16_as_ushort(d_Blo[src]);
        tile[j][threadIdx.x] = ((uint32_t)hb << 16) | lb;
    }
    __syncthreads();
    int l = y0 + threadIdx.x;
    for (int j = threadIdx.y; j < 32; j += 8) {
        int gn = blockIdx.x * 32 + j;
        uint32_t w = tile[threadIdx.x][j];
        d_BThi[(size_t)gn * LL + l] = __ushort_as_bfloat16((uint16_t)(w >> 16));
        d_BTlo[(size_t)gn * LL + l] = __ushort_as_bfloat16((uint16_t)(w & 0xffff));
    }
}

// xdt^T and (xdt*decay)^T hi/lo, computing xdt = conv*dt on the fly
__global__ void xtrans_kernel() {
    __shared__ float tile[32][33];
    int x = blockIdx.x * 32 + threadIdx.x;   // hp
    int y0 = blockIdx.y * 32;                // l
    int hload = x >> 6;
    for (int j = threadIdx.y; j < 32; j += 8)
        tile[j][threadIdx.x] = d_conv[(size_t)(y0 + j) * CONVDIM_ + x] *
                               d_dt[(size_t)(y0 + j) * HH + hload];
    __syncthreads();
    int l = y0 + threadIdx.x;
    int lastl = l | (CSZ - 1);
    for (int j = threadIdx.y; j < 32; j += 8) {
        int hp = blockIdx.x * 32 + j;
        int h = hp >> 6;
        float v = tile[threadIdx.x][j];
        __nv_bfloat16 hh, ll;
        split2(v, hh, ll);
        d_xThi[(size_t)hp * LL + l] = hh;
        d_xTlo[(size_t)hp * LL + l] = ll;
        float dec = __expf(d_Acs[(size_t)h * LL + lastl] - d_Acs[(size_t)h * LL + l]);
        split2(v * dec, hh, ll);
        d_xdThi[(size_t)hp * LL + l] = hh;
        d_xdTlo[(size_t)hp * LL + l] = ll;
    }
}

// inter-chunk recurrence; writes prev splits directly
__global__ void state_scan_kernel() {
    int t = blockIdx.x * blockDim.x + threadIdx.x;
    if (t >= HH * PP * NST) return;
    int n = t & 127, p = (t >> 7) & 63, h = t >> 13;
    float prev = 0.f;
#pragma unroll
    for (int c = 0; c < NCH; c++) {
        size_t idx = ((size_t)(c * HH + h) * PP + p) * NST + n;
        __nv_bfloat16 hh, ll;
        split2(prev, hh, ll);
        d_pvhi[idx] = hh;
        d_pvlo[idx] = ll;
        float cd = __expf(d_Acs[(size_t)h * LL + c * CSZ + 255]);
        prev = prev * cd + d_states[idx];
    }
}

// ============================================================================
// Fused scores + Y_diag + Y_off + D*x kernel (R11 proven version)
// ============================================================================
#define CK_ROWB 80
#define CK_STAGE (4 * 128 * CK_ROWB)
#define CK_SROW 272
#define CK_SOFF (2 * CK_STAGE)
#define CK_SBYT (128 * CK_SROW)
#define CK_XOFF (CK_SOFF + 2 * CK_SBYT)
#define CK_XBYT (64 * CK_SROW)
#define CK_PVOFF (CK_XOFF + 2 * CK_XBYT)   // 186368
#define CK_PVBYT (64 * CK_SROW)            // 17408
#define CK_SMEM (CK_PVOFF + 2 * CK_PVBYT)  // 221184

__global__ __launch_bounds__(256) void chunk_kernel(const float* __restrict__ Dvec) {
    const int lhalf = blockIdx.x;
    const int z = blockIdx.y;
    const int c = z >> 6, h = z & 63, g = h >> 3;
    extern __shared__ char sm[];
    const uint32_t sb = smem_u32(sm);
    const int tid = threadIdx.x;
    const int wid = tid >> 5, lane = tid & 31;
    const int quad = lane >> 3, qj = lane & 7;
    const int wy = wid & 3, wx = wid >> 2;
    const int l0 = c * CSZ + lhalf * 128;

    float yacc[2][4][4];
    float yoacc[2][4][4];
#pragma unroll
    for (int i = 0; i < 2; i++)
#pragma unroll
        for (int j = 0; j < 4; j++)
#pragma unroll
            for (int t = 0; t < 4; t++) { yacc[i][j][t] = 0.f; yoacc[i][j][t] = 0.f; }

    const float* acsH = d_Acs + (size_t)h * LL + c * CSZ;

    // preload prev[p][n] tile (64 x 128, hi/lo)
#pragma unroll
    for (int rep = 0; rep < 4; rep++) {
        int slot = tid + rep * 256;
        int row = slot >> 4, c16 = (slot & 15) * 16;
        size_t off = (size_t)z * 8192 + row * 128 + (c16 >> 1);
        cpa16(sb + CK_PVOFF + row * CK_SROW + c16, d_pvhi + off);
        cpa16(sb + CK_PVOFF + CK_PVBYT + row * CK_SROW + c16, d_pvlo + off);
    }

    for (int sh = 0; sh <= lhalf; sh++) {
        const int s0 = c * CSZ + sh * 128;
        float acc[2][8][4];
#pragma unroll
        for (int i = 0; i < 2; i++)
#pragma unroll
            for (int j = 0; j < 8; j++)
#pragma unroll
                for (int t = 0; t < 4; t++) acc[i][j][t] = 0.f;

#pragma unroll
        for (int rep = 0; rep < 4; rep++) {
            int slot = tid + rep * 256;
            int row = slot >> 4, c16 = (slot & 15) * 16;
            size_t off = (size_t)(h * 64 + row) * LL + s0 + (c16 >> 1);
            cpa16(sb + CK_XOFF + row * CK_SROW + c16, d_xThi + off);
            cpa16(sb + CK_XOFF + CK_XBYT + row * CK_SROW + c16, d_xTlo + off);
        }
        {
            const uint32_t base = sb + 0 * CK_STAGE;
#pragma unroll
            for (int rep = 0; rep < 2; rep++) {
                int slot = tid + rep * 256;
                int row = slot >> 2, c16 = (slot & 3) * 16;
                int kofe = 0 * 32 + (c16 >> 1);
                size_t crow = (size_t)(l0 + row) * 1024 + g * 128 + kofe;
                size_t brow = (size_t)(s0 + row) * 1024 + g * 128 + kofe;
                cpa16(base + row * CK_ROWB + c16, d_Chi2 + crow);
                cpa16(base + 10240 + row * CK_ROWB + c16, d_Clo2 + crow);
                cpa16(base + 20480 + row * CK_ROWB + c16, d_Bhi + brow);
                cpa16(base + 30720 + row * CK_ROWB + c16, d_Blo + brow);
            }
        }
        CP_COMMIT();
        {
            const uint32_t base = sb + 1 * CK_STAGE;
#pragma unroll
            for (int rep = 0; rep < 2; rep++) {
                int slot = tid + rep * 256;
                int row = slot >> 2, c16 = (slot & 3) * 16;
                int kofe = 1 * 32 + (c16 >> 1);
                size_t crow = (size_t)(l0 + row) * 1024 + g * 128 + kofe;
                size_t brow = (size_t)(s0 + row) * 1024 + g * 128 + kofe;
                cpa16(base + row * CK_ROWB + c16, d_Chi2 + crow);
                cpa16(base + 10240 + row * CK_ROWB + c16, d_Clo2 + crow);
                cpa16(base + 20480 + row * CK_ROWB + c16, d_Bhi + brow);
                cpa16(base + 30720 + row * CK_ROWB + c16, d_Blo + brow);
            }
        }
        CP_COMMIT();

        for (int kc = 0; kc < 4; kc++) {
            if (kc == 3) CP_WAIT0(); else CP_WAIT1();
            __syncthreads();
            {
                const uint32_t base = sb + (kc & 1) * CK_STAGE;
                const uint32_t Ch = base, Cl = base + 10240, Bh = base + 20480, Bl = base + 30720;
                const uint32_t Ph = sb + CK_PVOFF, Pl = sb + CK_PVOFF + CK_PVBYT;
#pragma unroll
                for (int k16 = 0; k16 < 2; k16++) {
                    const int k0 = k16 * 16;
                    uint32_t ah[2][4], al_[2][4];
#pragma unroll
                    for (int mt = 0; mt < 2; mt++) {
                        int row = wy * 32 + mt * 16 + ((quad & 1) ? 8 : 0) + qj;
                        int kel = k0 + ((quad & 2) ? 8 : 0);
                        LDSM4(ah[mt], Ch + row * CK_ROWB + kel * 2);
                        LDSM4(al_[mt], Cl + row * CK_ROWB + kel * 2);
                    }
                    uint32_t bh[8][2], bl[8][2];
#pragma unroll
                    for (int np = 0; np < 4; np++) {
                        int row = wx * 64 + np * 16 + ((quad & 2) ? 8 : 0) + qj;
                        int kel = k0 + ((quad & 1) ? 8 : 0);
                        uint32_t t[4];
                        LDSM4(t, Bh + row * CK_ROWB + kel * 2);
                        bh[np * 2][0] = t[0]; bh[np * 2][1] = t[1];
                        bh[np * 2 + 1][0] = t[2]; bh[np * 2 + 1][1] = t[3];
                        LDSM4(t, Bl + row * CK_ROWB + kel * 2);
                        bl[np * 2][0] = t[0]; bl[np * 2][1] = t[1];
                        bl[np * 2 + 1][0] = t[2]; bl[np * 2 + 1][1] = t[3];
                    }
#pragma unroll
                    for (int mt = 0; mt < 2; mt++)
#pragma unroll
                        for (int nt = 0; nt < 8; nt++) {
                            MMA16816(acc[mt][nt], ah[mt], bh[nt]);
                            MMA16816(acc[mt][nt], al_[mt], bh[nt]);
                            MMA16816(acc[mt][nt], ah[mt], bl[nt]);
                        }
                    // ---- fused Y_off: C fragments vs prev tile (once per block)
                    if (sh == 0) {
                        uint32_t ph[4][2], pl[4][2];
#pragma unroll
                        for (int np = 0; np < 2; np++) {
                            int row = wx * 32 + np * 16 + ((quad & 2) ? 8 : 0) + qj;
                            int kel = kc * 32 + k0 + ((quad & 1) ? 8 : 0);
                            uint32_t t[4];
                            LDSM4(t, Ph + row * CK_SROW + kel * 2);
                            ph[np * 2][0] = t[0]; ph[np * 2][1] = t[1];
                            ph[np * 2 + 1][0] = t[2]; ph[np * 2 + 1][1] = t[3];
                            LDSM4(t, Pl + row * CK_SROW + kel * 2);
                            pl[np * 2][0] = t[0]; pl[np * 2][1] = t[1];
                            pl[np * 2 + 1][0] = t[2]; pl[np * 2 + 1][1] = t[3];
                        }
#pragma unroll
                        for (int mt = 0; mt < 2; mt++)
#pragma unroll
                            for (int nt = 0; nt < 4; nt++) {
                                MMA16816(yoacc[mt][nt], ah[mt], ph[nt]);
                                MMA16816(yoacc[mt][nt], al_[mt], ph[nt]);
                                MMA16816(yoacc[mt][nt], ah[mt], pl[nt]);
                            }
                    }
                }
            }
            __syncthreads();
            if (kc + 2 < 4) {
                const uint32_t base = sb + ((kc + 2) & 1) * CK_STAGE;
#pragma unroll
                for (int rep = 0; rep < 2; rep++) {
                    int slot = tid + rep * 256;
                    int row = slot >> 2, c16 = (slot & 3) * 16;
                    int kofe = (kc + 2) * 32 + (c16 >> 1);
                    size_t crow = (size_t)(l0 + row) * 1024 + g * 128 + kofe;
                    size_t brow = (size_t)(s0 + row) * 1024 + g * 128 + kofe;
                    cpa16(base + row * CK_ROWB + c16, d_Chi2 + crow);
                    cpa16(base + 10240 + row * CK_ROWB + c16, d_Clo2 + crow);
                    cpa16(base + 20480 + row * CK_ROWB + c16, d_Bhi + brow);
                    cpa16(base + 30720 + row * CK_ROWB + c16, d_Blo + brow);
                }
                CP_COMMIT();
            }
        }

        {
            const bool diag = (sh == lhalf);
            char* Sh = sm + CK_SOFF;
            char* Sl = sm + CK_SOFF + CK_SBYT;
#pragma unroll
            for (int mt = 0; mt < 2; mt++) {
                int r0 = wy * 32 + mt * 16 + (lane >> 2);
#pragma unroll
                for (int half = 0; half < 2; half++) {
                    int r = r0 + half * 8;
                    float al = acsH[lhalf * 128 + r];
#pragma unroll
                    for (int nt = 0; nt < 8; nt++) {
                        int cc = wx * 64 + nt * 8 + (lane & 3) * 2;
                        float v0 = acc[mt][nt][half * 2 + 0];
                        float v1 = acc[mt][nt][half * 2 + 1];
                        float as0 = acsH[sh * 128 + cc];
                        float as1 = acsH[sh * 128 + cc + 1];
                        v0 = (!diag || (cc <= r)) ? v0 * __expf(al - as0) : 0.f;
                        v1 = (!diag || (cc + 1 <= r)) ? v1 * __expf(al - as1) : 0.f;
                        __nv_bfloat16 h0, h1, q0, q1;
                        split2(v0, h0, q0);
                        split2(v1, h1, q1);
                        *(__nv_bfloat162*)(Sh + r * CK_SROW + cc * 2) = __nv_bfloat162(h0, h1);
                        *(__nv_bfloat162*)(Sl + r * CK_SROW + cc * 2) = __nv_bfloat162(q0, q1);
                    }
                }
            }
        }
        __syncthreads();

        {
            const uint32_t Sh = sb + CK_SOFF, Sl = sb + CK_SOFF + CK_SBYT;
            const uint32_t Xh = sb + CK_XOFF, Xl = sb + CK_XOFF + CK_XBYT;
#pragma unroll 2
            for (int k16 = 0; k16 < 8; k16++) {
                const int k0 = k16 * 16;
                uint32_t ah[2][4], al_[2][4];
#pragma unroll
                for (int mt = 0; mt < 2; mt++) {
                    int row = wy * 32 + mt * 16 + ((quad & 1) ? 8 : 0) + qj;
                    int kel = k0 + ((quad & 2) ? 8 : 0);
                    LDSM4(ah[mt], Sh + row * CK_SROW + kel * 2);
                    LDSM4(al_[mt], Sl + row * CK_SROW + kel * 2);
                }
                uint32_t bh[4][2], bl[4][2];
#pragma unroll
                for (int np = 0; np < 2; np++) {
                    int row = wx * 32 + np * 16 + ((quad & 2) ? 8 : 0) + qj;
                    int kel = k0 + ((quad & 1) ? 8 : 0);
                    uint32_t t[4];
                    LDSM4(t, Xh + row * CK_SROW + kel * 2);
                    bh[np * 2][0] = t[0]; bh[np * 2][1] = t[1];
                    bh[np * 2 + 1][0] = t[2]; bh[np * 2 + 1][1] = t[3];
                    LDSM4(t, Xl + row * CK_SROW + kel * 2);
                    bl[np * 2][0] = t[0]; bl[np * 2][1] = t[1];
                    bl[np * 2 + 1][0] = t[2]; bl[np * 2 + 1][1] = t[3];
                }
#pragma unroll
                for (int mt = 0; mt < 2; mt++)
#pragma unroll
                    for (int nt = 0; nt < 4; nt++) {
                        MMA16816(yacc[mt][nt], ah[mt], bh[nt]);
                        MMA16816(yacc[mt][nt], al_[mt], bh[nt]);
                        MMA16816(yacc[mt][nt], ah[mt], bl[nt]);
                    }
            }
        }
        __syncthreads();
    }

    // ---- merged epilogue: Y = Y_diag + exp(Acs)*Y_off + D*x
    const float Dv = Dvec[h];
#pragma unroll
    for (int mt = 0; mt < 2; mt++)
#pragma unroll
        for (int nt = 0; nt < 4; nt++) {
            int r = wy * 32 + mt * 16 + (lane >> 2);
            int p = wx * 32 + nt * 8 + (lane & 3) * 2;
#pragma unroll
            for (int half = 0; half < 2; half++) {
                int rr = r + half * 8;
                int gl = l0 + rr;
                float sd = __expf(acsH[lhalf * 128 + rr]);
                float2 x = *(float2*)(d_conv + (size_t)gl * CONVDIM_ + h * 64 + p);
                float y0 = yacc[mt][nt][half * 2 + 0] + yoacc[mt][nt][half * 2 + 0] * sd + Dv * x.x;
                float y1 = yacc[mt][nt][half * 2 + 1] + yoacc[mt][nt][half * 2 + 1] * sd + Dv * x.y;
                *(float2*)(d_Y + (size_t)gl * INTER_ + h * 64 + p) = make_float2(y0, y1);
            }
        }
}

// ============================================================================
// states kernel
// ============================================================================
#define ST_STRIDE 30720
#define ST_SMEM   (2 * ST_STRIDE)

__global__ __launch_bounds__(256) void states_mma_kernel() {
    const int z = blockIdx.x;
    const int c = z >> 6, h = z & 63, g = h >> 3;
    extern __shared__ char sm[];
    const uint32_t sb = smem_u32(sm);
    const int tid = threadIdx.x;
    const int wid = tid >> 5, lane = tid & 31;
    const int quad = lane >> 3, qj = lane & 7;
    const int wy = wid & 1, wx = wid >> 1;

    float acc[2][4][4];
#pragma unroll
    for (int i = 0; i < 2; i++)
#pragma unroll
        for (int j = 0; j < 4; j++)
#pragma unroll
            for (int t = 0; t < 4; t++) acc[i][j][t] = 0.f;

    auto issue = [&](int kc) {
        const uint32_t base = sb + (kc & 1) * ST_STRIDE;
        {
            int slot = tid;
            int row = slot >> 2, c16 = (slot & 3) * 16;
            size_t off = (size_t)(h * 64 + row) * LL + c * CSZ + kc * 32 + (c16 >> 1);
            cpa16(base + row * 80 + c16, d_xdThi + off);
            cpa16(base + 5120 + row * 80 + c16, d_xdTlo + off);
        }
#pragma unroll
        for (int rep = 0; rep < 2; rep++) {
            int slot = tid + rep * 256;
            int row = slot >> 2, c16 = (slot & 3) * 16;
            size_t off = (size_t)(g * 128 + row) * LL + c * CSZ + kc * 32 + (c16 >> 1);
            cpa16(base + 10240 + row * 80 + c16, d_BThi + off);
            cpa16(base + 20480 + row * 80 + c16, d_BTlo + off);
        }
    };

    issue(0); CP_COMMIT();
    issue(1); CP_COMMIT();
    for (int kc = 0; kc < 8; kc++) {
        if (kc == 7) CP_WAIT0(); else CP_WAIT1();
        __syncthreads();
        {
            const uint32_t base = sb + (kc & 1) * ST_STRIDE;
            const uint32_t Ah = base, Al = base + 5120, Bh = base + 10240, Bl = base + 20480;
#pragma unroll
            for (int k16 = 0; k16 < 2; k16++) {
                const int k0 = k16 * 16;
                uint32_t ah[2][4], al_[2][4];
#pragma unroll
                for (int mt = 0; mt < 2; mt++) {
                    int row = wy * 32 + mt * 16 + ((quad & 1) ? 8 : 0) + qj;
                    int kel = k0 + ((quad & 2) ? 8 : 0);
                    LDSM4(ah[mt], Ah + row * 80 + kel * 2);
                    LDSM4(al_[mt], Al + row * 80 + kel * 2);
                }
                uint32_t bh[4][2], bl[4][2];
#pragma unroll
                for (int np = 0; np < 2; np++) {
                    int row = wx * 32 + np * 16 + ((quad & 2) ? 8 : 0) + qj;
                    int kel = k0 + ((quad & 1) ? 8 : 0);
                    uint32_t t[4];
                    LDSM4(t, Bh + row * 80 + kel * 2);
                    bh[np * 2][0] = t[0]; bh[np * 2][1] = t[1];
                    bh[np * 2 + 1][0] = t[2]; bh[np * 2 + 1][1] = t[3];
                    LDSM4(t, Bl + row * 80 + kel * 2);
                    bl[np * 2][0] = t[0]; bl[np * 2][1] = t[1];
                    bl[np * 2 + 1][0] = t[2]; bl[np * 2 + 1][1] = t[3];
                }
#pragma unroll
                for (int mt = 0; mt < 2; mt++)
#pragma unroll
                    for (int nt = 0; nt < 4; nt++) {
                        MMA16816(acc[mt][nt], ah[mt], bh[nt]);
                        MMA16816(acc[mt][nt], al_[mt], bh[nt]);
                        MMA16816(acc[mt][nt], ah[mt], bl[nt]);
                    }
            }
        }
        __syncthreads();
        if (kc + 2 < 8) { issue(kc + 2); CP_COMMIT(); }
    }

#pragma unroll
    for (int mt = 0; mt < 2; mt++)
#pragma unroll
        for (int nt = 0; nt < 4; nt++) {
            int p = wy * 32 + mt * 16 + (lane >> 2);
            int n = wx * 32 + nt * 8 + (lane & 3) * 2;
            *(float2*)(d_states + (size_t)z * 8192 + p * 128 + n) =
                make_float2(acc[mt][nt][0], acc[mt][nt][1]);
            *(float2*)(d_states + (size_t)z * 8192 + (p + 8) * 128 + n) =
                make_float2(acc[mt][nt][2], acc[mt][nt][3]);
        }
}

// ============================================================================
// gated group RMS norm — writes GEMM2 A-operand splits directly
// ============================================================================
__global__ __launch_bounds__(256) void norm_kernel(const float* __restrict__ norm_weight) {
    __shared__ float gbuf[INTER_];
    __shared__ float rs[GG];
    int l = blockIdx.x, tid = threadIdx.x;
    for (int i = tid; i < INTER_; i += 256) {
        float y = d_Y[(size_t)l * INTER_ + i];
        float gt = d_proj[(size_t)l * PROJ_ + i];
        float sg = 1.f / (1.f + __expf(-gt));
        gbuf[i] = y * gt * sg;
    }
    __syncthreads();
    int w = tid >> 5, lane = tid & 31;
    float ss = 0.f;
    for (int j = lane; j < 512; j += 32) { float v = gbuf[w * 512 + j]; ss += v * v; }
#pragma unroll
    for (int o = 16; o > 0; o >>= 1) ss += __shfl_xor_sync(0xffffffffu, ss, o);
    if (lane == 0) rs[w] = rsqrtf(ss * (1.f / 512.f) + 1e-5f);
    __syncthreads();
    for (int i = tid; i < INTER_; i += 256) {
        float v = gbuf[i] * rs[i >> 9] * norm_weight[i];
        __nv_bfloat16 h, lo;
        split2(v, h, lo);
        d_A2hi[(size_t)l * INTER_ + i] = h;
        d_A2lo[(size_t)l * INTER_ + i] = lo;
    }
}

// ============================================================================
extern "C" void kernel_launch(void* const* d_in, const int* in_sizes, int n_in,
                              void* d_out, int out_size) {
    (void)in_sizes; (void)n_in; (void)out_size;
    const float* hidden      = (const float*)d_in[0];
    const float* W_in        = (const float*)d_in[1];
    const float* conv_w      = (const float*)d_in[2];
    const float* conv_b      = (const float*)d_in[3];
    const float* dt_bias     = (const float*)d_in[4];
    const float* A_log       = (const float*)d_in[5];
    const float* Dvec        = (const float*)d_in[6];
    const float* norm_weight = (const float*)d_in[7];
    const float* W_out       = (const float*)d_in[8];
    float* out = (float*)d_out;

    float *p_proj = nullptr;
    __nv_bfloat16 *pA1h, *pA1l, *pW1h, *pW1l, *pA2h, *pA2l, *pW2h, *pW2l;
    cudaGetSymbolAddress((void**)&p_proj, d_proj);
    cudaGetSymbolAddress((void**)&pA1h, d_A1hi);
    cudaGetSymbolAddress((void**)&pA1l, d_A1lo);
    cudaGetSymbolAddress((void**)&pW1h, d_W1hi);
    cudaGetSymbolAddress((void**)&pW1l, d_W1lo);
    cudaGetSymbolAddress((void**)&pA2h, d_A2hi);
    cudaGetSymbolAddress((void**)&pA2l, d_A2lo);
    cudaGetSymbolAddress((void**)&pW2h, d_W2hi);
    cudaGetSymbolAddress((void**)&pW2l, d_W2lo);

    cudaFuncSetAttribute(gemm_mma, cudaFuncAttributeMaxDynamicSharedMemorySize, MM_SMEM);
    cudaFuncSetAttribute(chunk_kernel, cudaFuncAttributeMaxDynamicSharedMemorySize, CK_SMEM);
    cudaFuncSetAttribute(states_mma_kernel, cudaFuncAttributeMaxDynamicSharedMemorySize, ST_SMEM);

    // 0) splits for big GEMM operands
    { int n4 = (LL * DMODEL) / 4;    cvt_kernel<<<(n4 + 255) / 256, 256>>>(hidden, pA1h, pA1l, n4); }
    { int n4 = (PROJ_ * DMODEL) / 4; cvt_kernel<<<(n4 + 255) / 256, 256>>>(W_in, pW1h, pW1l, n4); }
    { int n4 = (DMODEL * INTER_) / 4; cvt_kernel<<<(n4 + 255) / 256, 256>>>(W_out, pW2h, pW2l, n4); }
    // 1) input projection
    {
        dim3 grid(LL / 128, (PROJ_ + 127) / 128);
        gemm_mma<<<grid, 256, MM_SMEM>>>(pA1h, pA1l, pW1h, pW1l, p_proj, LL, PROJ_, DMODEL);
    }
    // 2-3) dt + cumsum (warp-scan), conv(+BC splits, x-only fp32 store)
    dtacs_kernel<<<NCH * HH / 8, 256>>>(dt_bias, A_log);
    {
        dim3 grid(CONVDIM_ / 256, LL / 4);
        conv_kernel<<<grid, 256>>>(conv_w, conv_b);
    }
    // 4) transposed operand prep (btrans = pure bf16 transpose now)
    { dim3 grid(1024 / 32, LL / 32); btrans_kernel<<<grid, dim3(32, 8)>>>(); }
    { dim3 grid(INTER_ / 32, LL / 32); xtrans_kernel<<<grid, dim3(32, 8)>>>(); }
    // 5) states + scan (produces prev splits needed by fused chunk)
    states_mma_kernel<<<NBATCH, 256, ST_SMEM>>>();
    state_scan_kernel<<<(HH * PP * NST) / 256, 256>>>();
    // 6) fused scores + Y_diag + Y_off + D*x
    chunk_kernel<<<dim3(2, NBATCH), 256, CK_SMEM>>>(Dvec);
    // 7) norm (+A2 splits)
    norm_kernel<<<LL, 256>>>(norm_weight);
    // 8) output projection
    {
        dim3 grid(LL / 128, DMODEL / 128);
        gemm_mma<<<grid, 256, MM_SMEM>>>(pA2h, pA2l, pW2h, pW2l, out, LL, DMODEL, INTER_);
    }
}